// round 1
// baseline (speedup 1.0000x reference)
#include <cuda_runtime.h>
#include <cstddef>

// Problem dims
#define B_ 256
#define N_ 256
#define D_ 1024
#define S_ 1024

// Scratch (device globals — no allocations allowed)
__device__ float g_A[B_ * S_];   // state @ Q^T   [256,1024]
__device__ float g_M[B_ * N_];   // A @ K         [256,256]

// ---------------------------------------------------------------------------
// gemm_nt: g_A[m][n] = sum_k state[m][k] * Q[n][k]   (M=256, N=1024, K=1024)
// 64x64 tile, 256 threads, 4x4 microtile
// ---------------------------------------------------------------------------
__global__ void gemm_nt_kernel(const float* __restrict__ A,
                               const float* __restrict__ Bm) {
    __shared__ float As[16][64];
    __shared__ float Bs[16][64];
    const int m0 = blockIdx.y * 64;
    const int n0 = blockIdx.x * 64;
    const int t  = threadIdx.x;
    const int tx = t % 16, ty = t / 16;
    const int lk = t % 16, lr = t / 16;

    float acc[4][4] = {};

    for (int k0 = 0; k0 < S_; k0 += 16) {
#pragma unroll
        for (int j = 0; j < 4; j++) {
            As[lk][lr + 16 * j] = A[(size_t)(m0 + lr + 16 * j) * S_ + k0 + lk];
            Bs[lk][lr + 16 * j] = Bm[(size_t)(n0 + lr + 16 * j) * S_ + k0 + lk];
        }
        __syncthreads();
#pragma unroll
        for (int k = 0; k < 16; k++) {
            float a[4], b[4];
#pragma unroll
            for (int x = 0; x < 4; x++) a[x] = As[k][ty + 16 * x];
#pragma unroll
            for (int y = 0; y < 4; y++) b[y] = Bs[k][tx + 16 * y];
#pragma unroll
            for (int x = 0; x < 4; x++)
#pragma unroll
                for (int y = 0; y < 4; y++)
                    acc[x][y] = fmaf(a[x], b[y], acc[x][y]);
        }
        __syncthreads();
    }
#pragma unroll
    for (int x = 0; x < 4; x++)
#pragma unroll
        for (int y = 0; y < 4; y++)
            g_A[(size_t)(m0 + ty + 16 * x) * S_ + n0 + tx + 16 * y] = acc[x][y];
}

// ---------------------------------------------------------------------------
// gemm_nn: g_M[m][n] = sum_k g_A[m][k] * Kmat[k][n]  (M=256, N=256, K=1024)
// ---------------------------------------------------------------------------
__global__ void gemm_nn_kernel(const float* __restrict__ Bm) {
    __shared__ float As[16][64];
    __shared__ float Bs[16][64];
    const int m0 = blockIdx.y * 64;
    const int n0 = blockIdx.x * 64;
    const int t  = threadIdx.x;
    const int tx = t % 16, ty = t / 16;
    const int lk = t % 16, lr = t / 16;
    const int bk = t / 64, bn = t % 64;

    float acc[4][4] = {};

    for (int k0 = 0; k0 < S_; k0 += 16) {
#pragma unroll
        for (int j = 0; j < 4; j++)
            As[lk][lr + 16 * j] = g_A[(size_t)(m0 + lr + 16 * j) * S_ + k0 + lk];
#pragma unroll
        for (int j = 0; j < 4; j++)
            Bs[bk + 4 * j][bn] = Bm[(size_t)(k0 + bk + 4 * j) * N_ + n0 + bn];
        __syncthreads();
#pragma unroll
        for (int k = 0; k < 16; k++) {
            float a[4], b[4];
#pragma unroll
            for (int x = 0; x < 4; x++) a[x] = As[k][ty + 16 * x];
#pragma unroll
            for (int y = 0; y < 4; y++) b[y] = Bs[k][tx + 16 * y];
#pragma unroll
            for (int x = 0; x < 4; x++)
#pragma unroll
                for (int y = 0; y < 4; y++)
                    acc[x][y] = fmaf(a[x], b[y], acc[x][y]);
        }
        __syncthreads();
    }
#pragma unroll
    for (int x = 0; x < 4; x++)
#pragma unroll
        for (int y = 0; y < 4; y++)
            g_M[(size_t)(m0 + ty + 16 * x) * N_ + n0 + tx + 16 * y] = acc[x][y];
}

// ---------------------------------------------------------------------------
// Big batched GEMM:  Wlogits[i][b][d] = sum_n g_M[b][n] * FV[i][n][d]
// grid (d-tiles=8, b-tiles=2, i=256), block 256 threads, 128x128 tile,
// 8x8 microtile (strided mapping), kc=16.
// ---------------------------------------------------------------------------
__global__ void big_gemm_kernel(const float* __restrict__ FV,
                                float* __restrict__ Wout) {
    __shared__ float As[16][128];
    __shared__ float Bs[16][128];

    const int i  = blockIdx.z;
    const int b0 = blockIdx.y * 128;
    const int d0 = blockIdx.x * 128;
    const float* fv = FV + (size_t)i * N_ * D_;

    const int t  = threadIdx.x;
    const int tx = t % 16, ty = t / 16;

    // A loads: 128 rows x 16 k per chunk (scalar, coalesced over k)
    const int la_k = t % 16;
    const int la_r = t / 16;         // + 16*j, j=0..7
    // B loads: 16 rows(k) x 128 cols(d), float4 over d
    const int lb_k  = t / 32;        // 0..7 (+8 on second pass)
    const int lb_d4 = t % 32;        // float4 index

    float acc[8][8] = {};

    for (int k0 = 0; k0 < N_; k0 += 16) {
#pragma unroll
        for (int j = 0; j < 8; j++)
            As[la_k][la_r + 16 * j] =
                g_M[(size_t)(b0 + la_r + 16 * j) * N_ + k0 + la_k];
#pragma unroll
        for (int j = 0; j < 2; j++) {
            int kk = lb_k + 8 * j;
            float4 v = *reinterpret_cast<const float4*>(
                &fv[(size_t)(k0 + kk) * D_ + d0 + lb_d4 * 4]);
            *reinterpret_cast<float4*>(&Bs[kk][lb_d4 * 4]) = v;
        }
        __syncthreads();
#pragma unroll
        for (int k = 0; k < 16; k++) {
            float a[8], b[8];
#pragma unroll
            for (int x = 0; x < 8; x++) a[x] = As[k][ty + 16 * x];
#pragma unroll
            for (int y = 0; y < 8; y++) b[y] = Bs[k][tx + 16 * y];
#pragma unroll
            for (int x = 0; x < 8; x++)
#pragma unroll
                for (int y = 0; y < 8; y++)
                    acc[x][y] = fmaf(a[x], b[y], acc[x][y]);
        }
        __syncthreads();
    }

    float* wp = Wout + (size_t)i * N_ * D_;
#pragma unroll
    for (int x = 0; x < 8; x++)
#pragma unroll
        for (int y = 0; y < 8; y++)
            wp[(size_t)(b0 + ty + 16 * x) * D_ + d0 + tx + 16 * y] = acc[x][y];
}

// ---------------------------------------------------------------------------
// Softmax over d (in place on W) + context accumulation.
// grid = 256 (i), block = 1024 threads (thread = d).
//   context[i][d] = sum_b softmax(W[i][b][:])[d] * FV[i][b][d]
// ---------------------------------------------------------------------------
__global__ void softmax_ctx_kernel(const float* __restrict__ FV,
                                   float* __restrict__ out) {
    const int i = blockIdx.x;
    const int d = threadIdx.x;
    float* Wp = out + (size_t)B_ * D_ + (size_t)i * N_ * D_;
    const float* fv = FV + (size_t)i * N_ * D_;

    __shared__ float red_m[32];
    __shared__ float red_s[32];
    const int lane = d & 31;
    const int warp = d >> 5;

    float ctx = 0.f;

    for (int b = 0; b < N_; b++) {
        float z = Wp[(size_t)b * D_ + d];

        // block max
        float m = z;
#pragma unroll
        for (int o = 16; o > 0; o >>= 1)
            m = fmaxf(m, __shfl_xor_sync(0xffffffffu, m, o));
        if (lane == 0) red_m[warp] = m;
        __syncthreads();
        if (warp == 0) {
            float v = red_m[lane];
#pragma unroll
            for (int o = 16; o > 0; o >>= 1)
                v = fmaxf(v, __shfl_xor_sync(0xffffffffu, v, o));
            if (lane == 0) red_m[0] = v;
        }
        __syncthreads();
        m = red_m[0];

        float e = __expf(z - m);

        // block sum
        float s = e;
#pragma unroll
        for (int o = 16; o > 0; o >>= 1)
            s += __shfl_xor_sync(0xffffffffu, s, o);
        if (lane == 0) red_s[warp] = s;
        __syncthreads();
        if (warp == 0) {
            float v = red_s[lane];
#pragma unroll
            for (int o = 16; o > 0; o >>= 1)
                v += __shfl_xor_sync(0xffffffffu, v, o);
            if (lane == 0) red_s[0] = v;
        }
        __syncthreads();
        s = red_s[0];

        float w = e * __frcp_rn(s);
        Wp[(size_t)b * D_ + d] = w;
        ctx = fmaf(w, fv[(size_t)b * D_ + d], ctx);
    }

    out[(size_t)i * D_ + d] = ctx;
}

// ---------------------------------------------------------------------------
extern "C" void kernel_launch(void* const* d_in, const int* in_sizes, int n_in,
                              void* d_out, int out_size) {
    const float* FV    = (const float*)d_in[0];  // [256,256,1024]
    const float* state = (const float*)d_in[1];  // [256,1024]
    const float* Q     = (const float*)d_in[2];  // [1024,1024]
    const float* Kmat  = (const float*)d_in[3];  // [1024,256]
    float* out = (float*)d_out;                  // [context | W]

    // 1) A = state @ Q^T  -> g_A
    gemm_nt_kernel<<<dim3(S_ / 64, B_ / 64), 256>>>(state, Q);
    // 2) M = A @ K        -> g_M
    gemm_nn_kernel<<<dim3(N_ / 64, B_ / 64), 256>>>(Kmat);
    // 3) W logits = M @ FV[i]  (written to W region of out)
    big_gemm_kernel<<<dim3(D_ / 128, N_ / 128, B_), 256>>>(
        FV, out + (size_t)B_ * D_);
    // 4) softmax over d (in place) + context reduction
    softmax_ctx_kernel<<<B_, D_>>>(FV, out);
}

// round 3
// speedup vs baseline: 1.8959x; 1.8959x over previous
#include <cuda_runtime.h>
#include <cuda_fp16.h>
#include <cstdint>
#include <cstddef>

#define B_ 256
#define N_ 256
#define D_ 1024
#define S_ 1024

// ---------------------------------------------------------------------------
// Scratch (device globals — allocations are forbidden)
// ---------------------------------------------------------------------------
__device__ float g_A[B_ * S_];                 // state @ Q^T
__device__ __align__(16) __half g_Mh[B_ * N_]; // hi(M)
__device__ __align__(16) __half g_Ml[B_ * N_]; // lo(M)

// ---------------------------------------------------------------------------
// PTX helpers (baseline ISA only: ldmatrix / mma.sync / cp.async / cluster)
// ---------------------------------------------------------------------------
__device__ __forceinline__ uint32_t smem_u32(const void* p) {
    uint32_t a;
    asm("{ .reg .u64 t; cvta.to.shared.u64 t, %1; cvt.u32.u64 %0, t; }"
        : "=r"(a) : "l"(p));
    return a;
}
__device__ __forceinline__ void cp16(uint32_t dst, const void* src) {
    asm volatile("cp.async.cg.shared.global [%0], [%1], 16;" :: "r"(dst), "l"(src));
}
#define CP_COMMIT() asm volatile("cp.async.commit_group;" ::: "memory")
#define CP_WAIT0()  asm volatile("cp.async.wait_group 0;" ::: "memory")

__device__ __forceinline__ void ldsm_x4(uint32_t* r, uint32_t addr) {
    asm volatile("ldmatrix.sync.aligned.m8n8.x4.shared.b16 {%0,%1,%2,%3}, [%4];"
                 : "=r"(r[0]), "=r"(r[1]), "=r"(r[2]), "=r"(r[3]) : "r"(addr));
}
__device__ __forceinline__ void ldsm_x4_t(uint32_t* r, uint32_t addr) {
    asm volatile("ldmatrix.sync.aligned.m8n8.x4.trans.shared.b16 {%0,%1,%2,%3}, [%4];"
                 : "=r"(r[0]), "=r"(r[1]), "=r"(r[2]), "=r"(r[3]) : "r"(addr));
}
__device__ __forceinline__ void mma16816(float* c, const uint32_t* a, const uint32_t* b) {
    asm volatile(
        "mma.sync.aligned.m16n8k16.row.col.f32.f16.f16.f32 "
        "{%0,%1,%2,%3}, {%4,%5,%6,%7}, {%8,%9}, {%0,%1,%2,%3};"
        : "+f"(c[0]), "+f"(c[1]), "+f"(c[2]), "+f"(c[3])
        : "r"(a[0]), "r"(a[1]), "r"(a[2]), "r"(a[3]), "r"(b[0]), "r"(b[1]));
}
__device__ __forceinline__ void st_cluster_f32(uint32_t addr, uint32_t rank, float v) {
    asm volatile(
        "{ .reg .b32 ra; mapa.shared::cluster.u32 ra, %0, %1; "
        "st.shared::cluster.f32 [ra], %2; }"
        :: "r"(addr), "r"(rank), "f"(v) : "memory");
}
#define CLUSTER_ARV()  asm volatile("barrier.cluster.arrive.aligned;" ::: "memory")
#define CLUSTER_WAIT() asm volatile("barrier.cluster.wait.aligned;" ::: "memory")

// ---------------------------------------------------------------------------
// Small GEMM 1: g_A[m][n] = sum_k state[m][k] * Q[n][k]   (fp32)
// ---------------------------------------------------------------------------
__global__ void gemm_nt_kernel(const float* __restrict__ A,
                               const float* __restrict__ Bm) {
    __shared__ float As[16][64];
    __shared__ float Bs[16][64];
    const int m0 = blockIdx.y * 64, n0 = blockIdx.x * 64;
    const int t = threadIdx.x;
    const int tx = t % 16, ty = t / 16;
    const int lk = t % 16, lr = t / 16;
    float acc[4][4] = {};
    for (int k0 = 0; k0 < S_; k0 += 16) {
#pragma unroll
        for (int j = 0; j < 4; j++) {
            As[lk][lr + 16 * j] = A[(size_t)(m0 + lr + 16 * j) * S_ + k0 + lk];
            Bs[lk][lr + 16 * j] = Bm[(size_t)(n0 + lr + 16 * j) * S_ + k0 + lk];
        }
        __syncthreads();
#pragma unroll
        for (int k = 0; k < 16; k++) {
            float a[4], b[4];
#pragma unroll
            for (int x = 0; x < 4; x++) a[x] = As[k][ty + 16 * x];
#pragma unroll
            for (int y = 0; y < 4; y++) b[y] = Bs[k][tx + 16 * y];
#pragma unroll
            for (int x = 0; x < 4; x++)
#pragma unroll
                for (int y = 0; y < 4; y++) acc[x][y] = fmaf(a[x], b[y], acc[x][y]);
        }
        __syncthreads();
    }
#pragma unroll
    for (int x = 0; x < 4; x++)
#pragma unroll
        for (int y = 0; y < 4; y++)
            g_A[(size_t)(m0 + ty + 16 * x) * S_ + n0 + tx + 16 * y] = acc[x][y];
}

// ---------------------------------------------------------------------------
// Small GEMM 2: M[m][n] = sum_k g_A[m][k] * Kmat[k][n]; split to fp16 hi/lo
// ---------------------------------------------------------------------------
__global__ void gemm_nn_kernel(const float* __restrict__ Bm) {
    __shared__ float As[16][64];
    __shared__ float Bs[16][64];
    const int m0 = blockIdx.y * 64, n0 = blockIdx.x * 64;
    const int t = threadIdx.x;
    const int tx = t % 16, ty = t / 16;
    const int lk = t % 16, lr = t / 16;
    const int bk = t / 64, bn = t % 64;
    float acc[4][4] = {};
    for (int k0 = 0; k0 < S_; k0 += 16) {
#pragma unroll
        for (int j = 0; j < 4; j++)
            As[lk][lr + 16 * j] = g_A[(size_t)(m0 + lr + 16 * j) * S_ + k0 + lk];
#pragma unroll
        for (int j = 0; j < 4; j++)
            Bs[bk + 4 * j][bn] = Bm[(size_t)(k0 + bk + 4 * j) * N_ + n0 + bn];
        __syncthreads();
#pragma unroll
        for (int k = 0; k < 16; k++) {
            float a[4], b[4];
#pragma unroll
            for (int x = 0; x < 4; x++) a[x] = As[k][ty + 16 * x];
#pragma unroll
            for (int y = 0; y < 4; y++) b[y] = Bs[k][tx + 16 * y];
#pragma unroll
            for (int x = 0; x < 4; x++)
#pragma unroll
                for (int y = 0; y < 4; y++) acc[x][y] = fmaf(a[x], b[y], acc[x][y]);
        }
        __syncthreads();
    }
#pragma unroll
    for (int x = 0; x < 4; x++)
#pragma unroll
        for (int y = 0; y < 4; y++) {
            float v = acc[x][y];
            __half h = __float2half_rn(v);
            __half l = __float2half_rn(v - __half2float(h));
            size_t idx = (size_t)(m0 + ty + 16 * x) * N_ + n0 + tx + 16 * y;
            g_Mh[idx] = h;
            g_Ml[idx] = l;
        }
}

// ---------------------------------------------------------------------------
// Fused: logits GEMM (mma.sync, fp16 3-way split) + cluster softmax + W + ctx
// Cluster = 8 CTAs = one i; CTA tile: m=256 (all b) x n=128 (d-slice), K=256.
// ---------------------------------------------------------------------------
// smem layout (bytes, dynamic):
#define SA_OFF   0
#define SA_STAGE 40960   // per stage: hi 256*80 + lo 256*80
#define SA_HL    20480
#define SA_PITCH 80      // 40 halves (32 data + 8 pad) -> conflict-free ldmatrix
#define SB_OFF   81920
#define SB_STAGE 17408   // per stage: hi 32*272 + lo 32*272
#define SB_HL    8704
#define SB_PITCH 272     // 136 halves (128 data + 8 pad)
#define STG_OFF  0       // epilogue stage [256][129] f32 (reuses pipeline smem)
#define STG_PITCH 129
#define RED1_OFF 132096  // float[8][256]
#define RED2_OFF 140288  // float[8][256]
#define GSUM_OFF 148480  // float[256]
#define CTXP_OFF 149504  // float[256]
#define SMEM_DYN 150528

__global__ void __cluster_dims__(8, 1, 1) __launch_bounds__(256, 1)
fused_attn(const float* __restrict__ FV, float* __restrict__ out) {
    extern __shared__ char smem[];
    const uint32_t sbase = smem_u32(smem);
    const int tid = threadIdx.x;
    const int lane = tid & 31, w = tid >> 5;
    const int i = blockIdx.y;
    const int rank = blockIdx.x;       // cluster rank = d-slice
    const int d0 = rank * 128;
    const float* fv = FV + (size_t)i * N_ * D_ + d0;  // [n][128] view, row stride D_

    float acc[4][8][4];
#pragma unroll
    for (int a = 0; a < 4; a++)
#pragma unroll
        for (int b = 0; b < 8; b++)
#pragma unroll
            for (int c = 0; c < 4; c++) acc[a][b][c] = 0.f;

    // A (M matrix) cp.async mapping: threads 0-127 -> hi, 128-255 -> lo
    const int ahl = tid >> 7;                    // 0 = hi, 1 = lo
    const int arow0 = (tid & 127) * 2;           // two rows per thread
    const char* asrc = ahl ? (const char*)g_Ml : (const char*)g_Mh;

    auto loadA = [&](int c, int s) {
        uint32_t dst0 = sbase + SA_OFF + s * SA_STAGE + ahl * SA_HL;
#pragma unroll
        for (int rr = 0; rr < 2; rr++) {
            int row = arow0 + rr;
#pragma unroll
            for (int q = 0; q < 4; q++)
                cp16(dst0 + row * SA_PITCH + q * 16,
                     asrc + (size_t)row * 512 + c * 64 + q * 16);
        }
        CP_COMMIT();
    };

    // B (FV) LDG prefetch regs
    const int rk = tid >> 3;                     // row within 32-row chunk
    const int jb = (tid & 7) * 4;                // float index base
    float4 bf[4];
    auto loadB = [&](int c) {
        const float4* src = (const float4*)(fv + (size_t)(c * 32 + rk) * D_);
#pragma unroll
        for (int it = 0; it < 4; it++) bf[it] = src[(jb >> 2) + it * 8];
    };

    loadA(0, 0);
    loadB(0);

    const int m0w = (w >> 1) * 64;
    const int n0w = (w & 1) * 64;
    const int kofB = (lane & 7) | (((lane >> 3) & 1) << 3);
    const int nofB = (lane >> 4) * 8;

#pragma unroll 1
    for (int c = 0; c < 8; c++) {
        const int s = c & 1;
        CP_WAIT0();
        __syncthreads();
        if (c < 7) loadA(c + 1, (c + 1) & 1);

        // convert + store B chunk to smem (hi/lo)
        {
            char* sbb = smem + SB_OFF + s * SB_STAGE + rk * SB_PITCH;
#pragma unroll
            for (int it = 0; it < 4; it++) {
                float4 v = bf[it];
                __half hx = __float2half_rn(v.x), hy = __float2half_rn(v.y);
                __half hz = __float2half_rn(v.z), hw = __float2half_rn(v.w);
                __half2 p0 = __halves2half2(hx, hy), p1 = __halves2half2(hz, hw);
                uint2 hiw = make_uint2(*(uint32_t*)&p0, *(uint32_t*)&p1);
                __half lx = __float2half_rn(v.x - __half2float(hx));
                __half ly = __float2half_rn(v.y - __half2float(hy));
                __half lz = __float2half_rn(v.z - __half2float(hz));
                __half lw = __float2half_rn(v.w - __half2float(hw));
                __half2 q0 = __halves2half2(lx, ly), q1 = __halves2half2(lz, lw);
                uint2 low = make_uint2(*(uint32_t*)&q0, *(uint32_t*)&q1);
                int off = (jb + it * 32) * 2;
                *(uint2*)(sbb + off) = hiw;
                *(uint2*)(sbb + SB_HL + off) = low;
            }
        }
        if (c < 7) loadB(c + 1);
        __syncthreads();

        const uint32_t sa_h = sbase + SA_OFF + s * SA_STAGE;
        const uint32_t sb_h = sbase + SB_OFF + s * SB_STAGE;
        const uint32_t aBase = sa_h + (m0w + (lane & 15)) * SA_PITCH + (lane >> 4) * 16;

#pragma unroll
        for (int ks = 0; ks < 2; ks++) {
            uint32_t aH[4][4], aL[4][4];
#pragma unroll
            for (int mf = 0; mf < 4; mf++) {
                uint32_t ad = aBase + mf * (16 * SA_PITCH) + ks * 32;
                ldsm_x4(aH[mf], ad);
                ldsm_x4(aL[mf], ad + SA_HL);
            }
#pragma unroll
            for (int nf2 = 0; nf2 < 4; nf2++) {
                uint32_t bad = sb_h + (ks * 16 + kofB) * SB_PITCH +
                               (n0w + nf2 * 16 + nofB) * 2;
                uint32_t bh[4], bl[4];
                ldsm_x4_t(bh, bad);
                ldsm_x4_t(bl, bad + SB_HL);
#pragma unroll
                for (int mf = 0; mf < 4; mf++) {
                    mma16816(acc[mf][2 * nf2],     aH[mf], bh);
                    mma16816(acc[mf][2 * nf2 + 1], aH[mf], bh + 2);
                    mma16816(acc[mf][2 * nf2],     aH[mf], bl);
                    mma16816(acc[mf][2 * nf2 + 1], aH[mf], bl + 2);
                    mma16816(acc[mf][2 * nf2],     aL[mf], bh);
                    mma16816(acc[mf][2 * nf2 + 1], aL[mf], bh + 2);
                }
            }
        }
    }

    // ---------------- epilogue ----------------
    __syncthreads();
    float* stg = (float*)smem;             // [256][129]
    float* red1 = (float*)(smem + RED1_OFF);
    float* red2 = (float*)(smem + RED2_OFF);
    float* gsum = (float*)(smem + GSUM_OFF);
    float* ctxp = (float*)(smem + CTXP_OFF);

    // dump accumulators
#pragma unroll
    for (int mf = 0; mf < 4; mf++) {
        int r0 = m0w + mf * 16 + (lane >> 2);
#pragma unroll
        for (int nf = 0; nf < 8; nf++) {
            int cix = n0w + nf * 8 + (lane & 3) * 2;
            stg[r0 * STG_PITCH + cix]           = acc[mf][nf][0];
            stg[r0 * STG_PITCH + cix + 1]       = acc[mf][nf][1];
            stg[(r0 + 8) * STG_PITCH + cix]     = acc[mf][nf][2];
            stg[(r0 + 8) * STG_PITCH + cix + 1] = acc[mf][nf][3];
        }
    }
    __syncthreads();

    // local row max (thread = row)
    float rm = -1e30f;
#pragma unroll 8
    for (int j = 0; j < 128; j++) rm = fmaxf(rm, stg[tid * STG_PITCH + j]);
    const uint32_t red1a = sbase + RED1_OFF + (rank * 256 + tid) * 4;
#pragma unroll
    for (int p = 0; p < 8; p++) st_cluster_f32(red1a, p, rm);
    CLUSTER_ARV(); CLUSTER_WAIT();
    float gmax = -1e30f;
#pragma unroll
    for (int p = 0; p < 8; p++) gmax = fmaxf(gmax, red1[p * 256 + tid]);

    // exp + local sum (overwrite stage with e)
    float sv = 0.f;
#pragma unroll 8
    for (int j = 0; j < 128; j++) {
        float e = __expf(stg[tid * STG_PITCH + j] - gmax);
        stg[tid * STG_PITCH + j] = e;
        sv += e;
    }
    const uint32_t red2a = sbase + RED2_OFF + (rank * 256 + tid) * 4;
#pragma unroll
    for (int p = 0; p < 8; p++) st_cluster_f32(red2a, p, sv);
    CLUSTER_ARV(); CLUSTER_WAIT();
    float gs = 0.f;
#pragma unroll
    for (int p = 0; p < 8; p++) gs += red2[p * 256 + tid];
    gsum[tid] = __frcp_rn(gs);
    __syncthreads();

    // W write + context accumulation
    const int half = tid >> 7;
    const int j = tid & 127;
    float* Wout = out + (size_t)B_ * D_ + ((size_t)i * N_) * D_ + d0;
    float ctx = 0.f;
#pragma unroll 4
    for (int rb = 0; rb < 128; rb++) {
        int row = rb * 2 + half;
        float wv = stg[row * STG_PITCH + j] * gsum[row];
        Wout[(size_t)row * D_ + j] = wv;
        ctx = fmaf(wv, fv[(size_t)row * D_ + j], ctx);
    }
    ctxp[tid] = ctx;
    __syncthreads();
    if (tid < 128)
        out[(size_t)i * D_ + d0 + tid] = ctxp[tid] + ctxp[tid + 128];
}

// ---------------------------------------------------------------------------
extern "C" void kernel_launch(void* const* d_in, const int* in_sizes, int n_in,
                              void* d_out, int out_size) {
    const float* FV    = (const float*)d_in[0];  // [256,256,1024]
    const float* state = (const float*)d_in[1];  // [256,1024]
    const float* Q     = (const float*)d_in[2];  // [1024,1024]
    const float* Kmat  = (const float*)d_in[3];  // [1024,256]
    float* out = (float*)d_out;                  // [context | W]

    cudaFuncSetAttribute(fused_attn, cudaFuncAttributeMaxDynamicSharedMemorySize,
                         SMEM_DYN);

    gemm_nt_kernel<<<dim3(S_ / 64, B_ / 64), 256>>>(state, Q);
    gemm_nn_kernel<<<dim3(N_ / 64, B_ / 64), 256>>>(Kmat);
    fused_attn<<<dim3(8, B_), 256, SMEM_DYN>>>(FV, out);
}

// round 4
// speedup vs baseline: 2.3625x; 1.2461x over previous
#include <cuda_runtime.h>
#include <cuda_fp16.h>
#include <cstdint>
#include <cstddef>

#define B_ 256
#define N_ 256
#define D_ 1024
#define S_ 1024

// ---------------------------------------------------------------------------
// Scratch (device globals — allocations are forbidden)
// ---------------------------------------------------------------------------
__device__ float g_A[B_ * S_];                 // state @ Q^T (atomic accum)
__device__ float g_Mf[B_ * N_];                // M fp32 (atomic accum)
__device__ __align__(16) __half g_Mh[B_ * N_]; // hi(M)
__device__ __align__(16) __half g_Ml[B_ * N_]; // lo(M)

// ---------------------------------------------------------------------------
// PTX helpers (baseline ISA: ldmatrix / mma.sync / cp.async / cluster)
// ---------------------------------------------------------------------------
__device__ __forceinline__ uint32_t smem_u32(const void* p) {
    uint32_t a;
    asm("{ .reg .u64 t; cvta.to.shared.u64 t, %1; cvt.u32.u64 %0, t; }"
        : "=r"(a) : "l"(p));
    return a;
}
__device__ __forceinline__ void cp16(uint32_t dst, const void* src) {
    asm volatile("cp.async.cg.shared.global [%0], [%1], 16;" :: "r"(dst), "l"(src));
}
#define CP_COMMIT() asm volatile("cp.async.commit_group;" ::: "memory")
#define CP_WAIT0()  asm volatile("cp.async.wait_group 0;" ::: "memory")

__device__ __forceinline__ void ldsm_x4(uint32_t* r, uint32_t addr) {
    asm volatile("ldmatrix.sync.aligned.m8n8.x4.shared.b16 {%0,%1,%2,%3}, [%4];"
                 : "=r"(r[0]), "=r"(r[1]), "=r"(r[2]), "=r"(r[3]) : "r"(addr));
}
__device__ __forceinline__ void ldsm_x4_t(uint32_t* r, uint32_t addr) {
    asm volatile("ldmatrix.sync.aligned.m8n8.x4.trans.shared.b16 {%0,%1,%2,%3}, [%4];"
                 : "=r"(r[0]), "=r"(r[1]), "=r"(r[2]), "=r"(r[3]) : "r"(addr));
}
__device__ __forceinline__ void mma16816(float* c, const uint32_t* a, const uint32_t* b) {
    asm volatile(
        "mma.sync.aligned.m16n8k16.row.col.f32.f16.f16.f32 "
        "{%0,%1,%2,%3}, {%4,%5,%6,%7}, {%8,%9}, {%0,%1,%2,%3};"
        : "+f"(c[0]), "+f"(c[1]), "+f"(c[2]), "+f"(c[3])
        : "r"(a[0]), "r"(a[1]), "r"(a[2]), "r"(a[3]), "r"(b[0]), "r"(b[1]));
}
__device__ __forceinline__ void st_cluster_f32(uint32_t addr, uint32_t rank, float v) {
    asm volatile(
        "{ .reg .b32 ra; mapa.shared::cluster.u32 ra, %0, %1; "
        "st.shared::cluster.f32 [ra], %2; }"
        :: "r"(addr), "r"(rank), "f"(v) : "memory");
}
#define CLUSTER_ARV()  asm volatile("barrier.cluster.arrive.aligned;" ::: "memory")
#define CLUSTER_WAIT() asm volatile("barrier.cluster.wait.aligned;" ::: "memory")

// ---------------------------------------------------------------------------
// zero scratch accumulators
// ---------------------------------------------------------------------------
__global__ void zero_scratch() {
    int idx = blockIdx.x * blockDim.x + threadIdx.x;
    if (idx < B_ * S_) g_A[idx] = 0.f;
    if (idx < B_ * N_) g_Mf[idx] = 0.f;
}

// ---------------------------------------------------------------------------
// Split-K GEMM 1: g_A[m][n] += sum_{k in slice} state[m][k] * Q[n][k]
// grid (16, 4, 8): 64x64 tiles, K slice 128
// ---------------------------------------------------------------------------
__global__ void gemm_nt_sk(const float* __restrict__ A,
                           const float* __restrict__ Bm) {
    __shared__ float As[16][64];
    __shared__ float Bs[16][64];
    const int m0 = blockIdx.y * 64, n0 = blockIdx.x * 64;
    const int kbase = blockIdx.z * 128;
    const int t = threadIdx.x;
    const int tx = t % 16, ty = t / 16;
    const int lk = t % 16, lr = t / 16;
    float acc[4][4] = {};
    for (int k0 = kbase; k0 < kbase + 128; k0 += 16) {
#pragma unroll
        for (int j = 0; j < 4; j++) {
            As[lk][lr + 16 * j] = A[(size_t)(m0 + lr + 16 * j) * S_ + k0 + lk];
            Bs[lk][lr + 16 * j] = Bm[(size_t)(n0 + lr + 16 * j) * S_ + k0 + lk];
        }
        __syncthreads();
#pragma unroll
        for (int k = 0; k < 16; k++) {
            float a[4], b[4];
#pragma unroll
            for (int x = 0; x < 4; x++) a[x] = As[k][ty + 16 * x];
#pragma unroll
            for (int y = 0; y < 4; y++) b[y] = Bs[k][tx + 16 * y];
#pragma unroll
            for (int x = 0; x < 4; x++)
#pragma unroll
                for (int y = 0; y < 4; y++) acc[x][y] = fmaf(a[x], b[y], acc[x][y]);
        }
        __syncthreads();
    }
#pragma unroll
    for (int x = 0; x < 4; x++)
#pragma unroll
        for (int y = 0; y < 4; y++)
            atomicAdd(&g_A[(size_t)(m0 + ty + 16 * x) * S_ + n0 + tx + 16 * y],
                      acc[x][y]);
}

// ---------------------------------------------------------------------------
// Split-K GEMM 2: g_Mf[m][n] += sum_{k in slice} g_A[m][k] * Kmat[k][n]
// grid (4, 4, 8)
// ---------------------------------------------------------------------------
__global__ void gemm_nn_sk(const float* __restrict__ Bm) {
    __shared__ float As[16][64];
    __shared__ float Bs[16][64];
    const int m0 = blockIdx.y * 64, n0 = blockIdx.x * 64;
    const int kbase = blockIdx.z * 128;
    const int t = threadIdx.x;
    const int tx = t % 16, ty = t / 16;
    const int lk = t % 16, lr = t / 16;
    const int bk = t / 64, bn = t % 64;
    float acc[4][4] = {};
    for (int k0 = kbase; k0 < kbase + 128; k0 += 16) {
#pragma unroll
        for (int j = 0; j < 4; j++)
            As[lk][lr + 16 * j] = g_A[(size_t)(m0 + lr + 16 * j) * S_ + k0 + lk];
#pragma unroll
        for (int j = 0; j < 4; j++)
            Bs[bk + 4 * j][bn] = Bm[(size_t)(k0 + bk + 4 * j) * N_ + n0 + bn];
        __syncthreads();
#pragma unroll
        for (int k = 0; k < 16; k++) {
            float a[4], b[4];
#pragma unroll
            for (int x = 0; x < 4; x++) a[x] = As[k][ty + 16 * x];
#pragma unroll
            for (int y = 0; y < 4; y++) b[y] = Bs[k][tx + 16 * y];
#pragma unroll
            for (int x = 0; x < 4; x++)
#pragma unroll
                for (int y = 0; y < 4; y++) acc[x][y] = fmaf(a[x], b[y], acc[x][y]);
        }
        __syncthreads();
    }
#pragma unroll
    for (int x = 0; x < 4; x++)
#pragma unroll
        for (int y = 0; y < 4; y++)
            atomicAdd(&g_Mf[(size_t)(m0 + ty + 16 * x) * N_ + n0 + tx + 16 * y],
                      acc[x][y]);
}

// ---------------------------------------------------------------------------
// convert M fp32 -> fp16 hi/lo
// ---------------------------------------------------------------------------
__global__ void convert_M() {
    int idx = blockIdx.x * blockDim.x + threadIdx.x;
    if (idx < B_ * N_) {
        float v = g_Mf[idx];
        __half h = __float2half_rn(v);
        __half l = __float2half_rn(v - __half2float(h));
        g_Mh[idx] = h;
        g_Ml[idx] = l;
    }
}

// ---------------------------------------------------------------------------
// Fused kernel: logits GEMM (fp16 3-way split) + cluster softmax + W + ctx
// Cluster = 8 CTAs (one i). CTA tile: m=256 (all b) x n=128 (d-slice), K=256.
// 512 threads = 16 warps: warp grid 8(m) x 2(n); warp tile 32x64.
// ---------------------------------------------------------------------------
#define SA_OFF   0
#define SA_STAGE 40960   // hi 256*80 + lo 256*80
#define SA_HL    20480
#define SA_PITCH 80
#define SB_OFF   81920
#define SB_STAGE 17408   // hi 32*272 + lo 32*272
#define SB_HL    8704
#define SB_PITCH 272
#define RED_OFF   116736 // float[256][2]  local pair reduce
#define RED1_OFF  118784 // float[8][256]  cluster max
#define RED2_OFF  126976 // float[8][256]  cluster sum
#define GV_OFF    135168 // float[256]     global max
#define INV_OFF   136192 // float[256]     1/sum
#define CTXR_OFF  137216 // float[8][128]  ctx partials
#define SMEM_DYN  141312

__global__ void __cluster_dims__(8, 1, 1) __launch_bounds__(512, 1)
fused_attn(const float* __restrict__ FV, float* __restrict__ out) {
    extern __shared__ char smem[];
    const uint32_t sbase = smem_u32(smem);
    const int tid = threadIdx.x;
    const int lane = tid & 31, w = tid >> 5;
    const int i = blockIdx.y;
    const int rank = blockIdx.x;
    const int d0 = rank * 128;
    const float* fv = FV + (size_t)i * N_ * D_ + d0;

    float acc[2][8][4];
#pragma unroll
    for (int a = 0; a < 2; a++)
#pragma unroll
        for (int b = 0; b < 8; b++)
#pragma unroll
            for (int c = 0; c < 4; c++) acc[a][b][c] = 0.f;

    // A loads: threads 0-255 hi, 256-511 lo; one row (64B) x4 cp16 each
    const int ahl = tid >> 8;
    const int arow = tid & 255;
    const char* asrc = ahl ? (const char*)g_Ml : (const char*)g_Mh;
    auto loadA = [&](int c, int s) {
        uint32_t dst0 = sbase + SA_OFF + s * SA_STAGE + ahl * SA_HL + arow * SA_PITCH;
        const char* src = asrc + (size_t)arow * 512 + c * 64;
#pragma unroll
        for (int q = 0; q < 4; q++) cp16(dst0 + q * 16, src + q * 16);
        CP_COMMIT();
    };

    // B loads: chunk = 32 rows x 128 floats; 512 threads x 2 float4
    const int rk = tid >> 4;          // row 0..31
    const int c4 = tid & 15;          // float4 col base
    float4 bf[2];
    auto loadB = [&](int c) {
        const float4* src = (const float4*)(fv + (size_t)(c * 32 + rk) * D_);
        bf[0] = src[c4];
        bf[1] = src[c4 + 16];
    };

    loadA(0, 0);
    loadB(0);

    const int m0w = (w >> 1) * 32;
    const int n0w = (w & 1) * 64;
    const int kofB = (lane & 7) | (((lane >> 3) & 1) << 3);
    const int nofB = (lane >> 4) * 8;

#pragma unroll 1
    for (int c = 0; c < 8; c++) {
        const int s = c & 1;
        CP_WAIT0();
        __syncthreads();
        if (c < 7) loadA(c + 1, (c + 1) & 1);

        // convert + store B chunk (hi/lo)
        {
            char* sbb = smem + SB_OFF + s * SB_STAGE + rk * SB_PITCH;
#pragma unroll
            for (int it = 0; it < 2; it++) {
                float4 v = bf[it];
                int j = (c4 + it * 16) * 4;      // float index in row
                __half hx = __float2half_rn(v.x), hy = __float2half_rn(v.y);
                __half hz = __float2half_rn(v.z), hw = __float2half_rn(v.w);
                __half2 p0 = __halves2half2(hx, hy), p1 = __halves2half2(hz, hw);
                uint2 hiw = make_uint2(*(uint32_t*)&p0, *(uint32_t*)&p1);
                __half lx = __float2half_rn(v.x - __half2float(hx));
                __half ly = __float2half_rn(v.y - __half2float(hy));
                __half lz = __float2half_rn(v.z - __half2float(hz));
                __half lw = __float2half_rn(v.w - __half2float(hw));
                __half2 q0 = __halves2half2(lx, ly), q1 = __halves2half2(lz, lw);
                uint2 low = make_uint2(*(uint32_t*)&q0, *(uint32_t*)&q1);
                *(uint2*)(sbb + j * 2) = hiw;
                *(uint2*)(sbb + SB_HL + j * 2) = low;
            }
        }
        if (c < 7) loadB(c + 1);
        __syncthreads();

        const uint32_t sa_h = sbase + SA_OFF + s * SA_STAGE;
        const uint32_t sb_h = sbase + SB_OFF + s * SB_STAGE;
        const uint32_t aBase = sa_h + (m0w + (lane & 15)) * SA_PITCH + (lane >> 4) * 16;

#pragma unroll
        for (int ks = 0; ks < 2; ks++) {
            uint32_t aH[2][4], aL[2][4];
#pragma unroll
            for (int mf = 0; mf < 2; mf++) {
                uint32_t ad = aBase + mf * (16 * SA_PITCH) + ks * 32;
                ldsm_x4(aH[mf], ad);
                ldsm_x4(aL[mf], ad + SA_HL);
            }
#pragma unroll
            for (int nf2 = 0; nf2 < 4; nf2++) {
                uint32_t bad = sb_h + (ks * 16 + kofB) * SB_PITCH +
                               (n0w + nf2 * 16 + nofB) * 2;
                uint32_t bh[4], bl[4];
                ldsm_x4_t(bh, bad);
                ldsm_x4_t(bl, bad + SB_HL);
#pragma unroll
                for (int mf = 0; mf < 2; mf++) {
                    mma16816(acc[mf][2 * nf2],     aH[mf], bh);
                    mma16816(acc[mf][2 * nf2 + 1], aH[mf], bh + 2);
                    mma16816(acc[mf][2 * nf2],     aH[mf], bl);
                    mma16816(acc[mf][2 * nf2 + 1], aH[mf], bl + 2);
                    mma16816(acc[mf][2 * nf2],     aL[mf], bh);
                    mma16816(acc[mf][2 * nf2 + 1], aL[mf], bh + 2);
                }
            }
        }
    }

    // ---------------- register-resident softmax epilogue ----------------
    float* red  = (float*)(smem + RED_OFF);    // [256][2]
    float* red1 = (float*)(smem + RED1_OFF);   // [8][256]
    float* red2 = (float*)(smem + RED2_OFF);
    float* gv   = (float*)(smem + GV_OFF);
    float* inv  = (float*)(smem + INV_OFF);
    float* ctxr = (float*)(smem + CTXR_OFF);   // [8][128]
    __syncthreads();

    // --- local row max (4 row-slots per thread: mf x half) ---
    float rmax[2][2];
#pragma unroll
    for (int mf = 0; mf < 2; mf++)
#pragma unroll
        for (int h = 0; h < 2; h++) {
            float m = -1e30f;
#pragma unroll
            for (int nf = 0; nf < 8; nf++)
                m = fmaxf(m, fmaxf(acc[mf][nf][2 * h], acc[mf][nf][2 * h + 1]));
            m = fmaxf(m, __shfl_xor_sync(0xffffffffu, m, 1));
            m = fmaxf(m, __shfl_xor_sync(0xffffffffu, m, 2));
            rmax[mf][h] = m;
        }
    if ((lane & 3) == 0) {
#pragma unroll
        for (int mf = 0; mf < 2; mf++)
#pragma unroll
            for (int h = 0; h < 2; h++) {
                int row = m0w + mf * 16 + (lane >> 2) + 8 * h;
                red[row * 2 + (w & 1)] = rmax[mf][h];
            }
    }
    __syncthreads();
    if (tid < 256) {
        float m = fmaxf(red[tid * 2], red[tid * 2 + 1]);
        const uint32_t a = sbase + RED1_OFF + (rank * 256 + tid) * 4;
#pragma unroll
        for (int p = 0; p < 8; p++) st_cluster_f32(a, p, m);
    }
    CLUSTER_ARV(); CLUSTER_WAIT();
    if (tid < 256) {
        float m = -1e30f;
#pragma unroll
        for (int p = 0; p < 8; p++) m = fmaxf(m, red1[p * 256 + tid]);
        gv[tid] = m;
    }
    __syncthreads();

    // --- exp (in registers) + local row sum ---
    float rsum[2][2];
#pragma unroll
    for (int mf = 0; mf < 2; mf++)
#pragma unroll
        for (int h = 0; h < 2; h++) {
            int row = m0w + mf * 16 + (lane >> 2) + 8 * h;
            float gm = gv[row];
            float s = 0.f;
#pragma unroll
            for (int nf = 0; nf < 8; nf++) {
                float e0 = __expf(acc[mf][nf][2 * h] - gm);
                float e1 = __expf(acc[mf][nf][2 * h + 1] - gm);
                acc[mf][nf][2 * h] = e0;
                acc[mf][nf][2 * h + 1] = e1;
                s += e0 + e1;
            }
            s += __shfl_xor_sync(0xffffffffu, s, 1);
            s += __shfl_xor_sync(0xffffffffu, s, 2);
            rsum[mf][h] = s;
        }
    if ((lane & 3) == 0) {
#pragma unroll
        for (int mf = 0; mf < 2; mf++)
#pragma unroll
            for (int h = 0; h < 2; h++) {
                int row = m0w + mf * 16 + (lane >> 2) + 8 * h;
                red[row * 2 + (w & 1)] = rsum[mf][h];
            }
    }
    __syncthreads();
    if (tid < 256) {
        float s = red[tid * 2] + red[tid * 2 + 1];
        const uint32_t a = sbase + RED2_OFF + (rank * 256 + tid) * 4;
#pragma unroll
        for (int p = 0; p < 8; p++) st_cluster_f32(a, p, s);
    }
    CLUSTER_ARV(); CLUSTER_WAIT();
    if (tid < 256) {
        float s = 0.f;
#pragma unroll
        for (int p = 0; p < 8; p++) s += red2[p * 256 + tid];
        inv[tid] = __frcp_rn(s);
    }
    __syncthreads();

    // --- W write + ctx accumulation from registers ---
    float* Wout = out + (size_t)B_ * D_ + (size_t)i * N_ * D_ + d0;
    float ctxc[16];
#pragma unroll
    for (int j = 0; j < 16; j++) ctxc[j] = 0.f;

#pragma unroll
    for (int mf = 0; mf < 2; mf++)
#pragma unroll
        for (int h = 0; h < 2; h++) {
            int row = m0w + mf * 16 + (lane >> 2) + 8 * h;
            float iv = inv[row];
            const float* fvr = fv + (size_t)row * D_;
            float* wr = Wout + (size_t)row * D_;
#pragma unroll
            for (int nf = 0; nf < 8; nf++) {
                int col = n0w + nf * 8 + (lane & 3) * 2;
                float w0 = acc[mf][nf][2 * h] * iv;
                float w1 = acc[mf][nf][2 * h + 1] * iv;
                *(float2*)(wr + col) = make_float2(w0, w1);
                float2 f = *(const float2*)(fvr + col);
                ctxc[nf * 2]     = fmaf(w0, f.x, ctxc[nf * 2]);
                ctxc[nf * 2 + 1] = fmaf(w1, f.y, ctxc[nf * 2 + 1]);
            }
        }
    // warp reduce over row-groups (lanes differing in lane>>2)
#pragma unroll
    for (int j = 0; j < 16; j++) {
        ctxc[j] += __shfl_xor_sync(0xffffffffu, ctxc[j], 4);
        ctxc[j] += __shfl_xor_sync(0xffffffffu, ctxc[j], 8);
        ctxc[j] += __shfl_xor_sync(0xffffffffu, ctxc[j], 16);
    }
    if (lane < 4) {
#pragma unroll
        for (int nf = 0; nf < 8; nf++) {
            int col = n0w + nf * 8 + lane * 2;
            ctxr[(w >> 1) * 128 + col]     = ctxc[nf * 2];
            ctxr[(w >> 1) * 128 + col + 1] = ctxc[nf * 2 + 1];
        }
    }
    __syncthreads();
    if (tid < 128) {
        float s = 0.f;
#pragma unroll
        for (int p = 0; p < 8; p++) s += ctxr[p * 128 + tid];
        out[(size_t)i * D_ + d0 + tid] = s;
    }
}

// ---------------------------------------------------------------------------
extern "C" void kernel_launch(void* const* d_in, const int* in_sizes, int n_in,
                              void* d_out, int out_size) {
    const float* FV    = (const float*)d_in[0];
    const float* state = (const float*)d_in[1];
    const float* Q     = (const float*)d_in[2];
    const float* Kmat  = (const float*)d_in[3];
    float* out = (float*)d_out;

    cudaFuncSetAttribute(fused_attn, cudaFuncAttributeMaxDynamicSharedMemorySize,
                         SMEM_DYN);

    zero_scratch<<<(B_ * S_ + 255) / 256, 256>>>();
    gemm_nt_sk<<<dim3(S_ / 64, B_ / 64, 8), 256>>>(state, Q);
    gemm_nn_sk<<<dim3(N_ / 64, B_ / 64, 8), 256>>>(Kmat);
    convert_M<<<(B_ * N_ + 255) / 256, 256>>>();
    fused_attn<<<dim3(8, B_), 512, SMEM_DYN>>>(FV, out);
}

// round 7
// speedup vs baseline: 3.0135x; 1.2756x over previous
#include <cuda_runtime.h>
#include <cuda_fp16.h>
#include <cstdint>
#include <cstddef>

#define B_ 256
#define N_ 256
#define D_ 1024
#define S_ 1024

// ---------------------------------------------------------------------------
// Scratch (device globals — allocations are forbidden)
// ---------------------------------------------------------------------------
__device__ float g_A[B_ * S_];                 // state @ Q^T (atomic accum)
__device__ float g_Mf[B_ * N_];                // M fp32 (atomic accum)
__device__ __align__(16) __half g_Mh[B_ * N_]; // hi(M)
__device__ __align__(16) __half g_Ml[B_ * N_]; // lo(M)
__device__ float g_ctx[2][B_ * D_];            // ctx partials per b-half

// ---------------------------------------------------------------------------
// PTX helpers (baseline ISA: ldmatrix / mma.sync / cp.async / cluster)
// ---------------------------------------------------------------------------
__device__ __forceinline__ uint32_t smem_u32(const void* p) {
    uint32_t a;
    asm("{ .reg .u64 t; cvta.to.shared.u64 t, %1; cvt.u32.u64 %0, t; }"
        : "=r"(a) : "l"(p));
    return a;
}
__device__ __forceinline__ void cp16(uint32_t dst, const void* src) {
    asm volatile("cp.async.cg.shared.global [%0], [%1], 16;" :: "r"(dst), "l"(src));
}
#define CP_COMMIT() asm volatile("cp.async.commit_group;" ::: "memory")
#define CP_WAIT0()  asm volatile("cp.async.wait_group 0;" ::: "memory")

__device__ __forceinline__ void ldsm_x4(uint32_t* r, uint32_t addr) {
    asm volatile("ldmatrix.sync.aligned.m8n8.x4.shared.b16 {%0,%1,%2,%3}, [%4];"
                 : "=r"(r[0]), "=r"(r[1]), "=r"(r[2]), "=r"(r[3]) : "r"(addr));
}
__device__ __forceinline__ void ldsm_x4_t(uint32_t* r, uint32_t addr) {
    asm volatile("ldmatrix.sync.aligned.m8n8.x4.trans.shared.b16 {%0,%1,%2,%3}, [%4];"
                 : "=r"(r[0]), "=r"(r[1]), "=r"(r[2]), "=r"(r[3]) : "r"(addr));
}
__device__ __forceinline__ void mma16816(float* c, const uint32_t* a, const uint32_t* b) {
    asm volatile(
        "mma.sync.aligned.m16n8k16.row.col.f32.f16.f16.f32 "
        "{%0,%1,%2,%3}, {%4,%5,%6,%7}, {%8,%9}, {%0,%1,%2,%3};"
        : "+f"(c[0]), "+f"(c[1]), "+f"(c[2]), "+f"(c[3])
        : "r"(a[0]), "r"(a[1]), "r"(a[2]), "r"(a[3]), "r"(b[0]), "r"(b[1]));
}
__device__ __forceinline__ void st_cluster_f32(uint32_t addr, uint32_t rank, float v) {
    asm volatile(
        "{ .reg .b32 ra; mapa.shared::cluster.u32 ra, %0, %1; "
        "st.shared::cluster.f32 [ra], %2; }"
        :: "r"(addr), "r"(rank), "f"(v) : "memory");
}
#define CLUSTER_ARV()  asm volatile("barrier.cluster.arrive.aligned;" ::: "memory")
#define CLUSTER_WAIT() asm volatile("barrier.cluster.wait.aligned;" ::: "memory")

// ---------------------------------------------------------------------------
// zero scratch accumulators
// ---------------------------------------------------------------------------
__global__ void zero_scratch() {
    int idx = blockIdx.x * blockDim.x + threadIdx.x;
    if (idx < B_ * S_) g_A[idx] = 0.f;
    if (idx < B_ * N_) g_Mf[idx] = 0.f;
}

// ---------------------------------------------------------------------------
// Split-K GEMM 1: g_A[m][n] += sum_{k slice} state[m][k] * Q[n][k]
// ---------------------------------------------------------------------------
__global__ void gemm_nt_sk(const float* __restrict__ A,
                           const float* __restrict__ Bm) {
    __shared__ float As[16][64];
    __shared__ float Bs[16][64];
    const int m0 = blockIdx.y * 64, n0 = blockIdx.x * 64;
    const int kbase = blockIdx.z * 128;
    const int t = threadIdx.x;
    const int tx = t % 16, ty = t / 16;
    const int lk = t % 16, lr = t / 16;
    float acc[4][4] = {};
    for (int k0 = kbase; k0 < kbase + 128; k0 += 16) {
#pragma unroll
        for (int j = 0; j < 4; j++) {
            As[lk][lr + 16 * j] = A[(size_t)(m0 + lr + 16 * j) * S_ + k0 + lk];
            Bs[lk][lr + 16 * j] = Bm[(size_t)(n0 + lr + 16 * j) * S_ + k0 + lk];
        }
        __syncthreads();
#pragma unroll
        for (int k = 0; k < 16; k++) {
            float a[4], b[4];
#pragma unroll
            for (int x = 0; x < 4; x++) a[x] = As[k][ty + 16 * x];
#pragma unroll
            for (int y = 0; y < 4; y++) b[y] = Bs[k][tx + 16 * y];
#pragma unroll
            for (int x = 0; x < 4; x++)
#pragma unroll
                for (int y = 0; y < 4; y++) acc[x][y] = fmaf(a[x], b[y], acc[x][y]);
        }
        __syncthreads();
    }
#pragma unroll
    for (int x = 0; x < 4; x++)
#pragma unroll
        for (int y = 0; y < 4; y++)
            atomicAdd(&g_A[(size_t)(m0 + ty + 16 * x) * S_ + n0 + tx + 16 * y],
                      acc[x][y]);
}

// ---------------------------------------------------------------------------
// Split-K GEMM 2: g_Mf[m][n] += sum_{k slice} g_A[m][k] * Kmat[k][n]
// ---------------------------------------------------------------------------
__global__ void gemm_nn_sk(const float* __restrict__ Bm) {
    __shared__ float As[16][64];
    __shared__ float Bs[16][64];
    const int m0 = blockIdx.y * 64, n0 = blockIdx.x * 64;
    const int kbase = blockIdx.z * 128;
    const int t = threadIdx.x;
    const int tx = t % 16, ty = t / 16;
    const int lk = t % 16, lr = t / 16;
    const int bk = t / 64, bn = t % 64;
    float acc[4][4] = {};
    for (int k0 = kbase; k0 < kbase + 128; k0 += 16) {
#pragma unroll
        for (int j = 0; j < 4; j++)
            As[lk][lr + 16 * j] = g_A[(size_t)(m0 + lr + 16 * j) * S_ + k0 + lk];
#pragma unroll
        for (int j = 0; j < 4; j++)
            Bs[bk + 4 * j][bn] = Bm[(size_t)(k0 + bk + 4 * j) * N_ + n0 + bn];
        __syncthreads();
#pragma unroll
        for (int k = 0; k < 16; k++) {
            float a[4], b[4];
#pragma unroll
            for (int x = 0; x < 4; x++) a[x] = As[k][ty + 16 * x];
#pragma unroll
            for (int y = 0; y < 4; y++) b[y] = Bs[k][tx + 16 * y];
#pragma unroll
            for (int x = 0; x < 4; x++)
#pragma unroll
                for (int y = 0; y < 4; y++) acc[x][y] = fmaf(a[x], b[y], acc[x][y]);
        }
        __syncthreads();
    }
#pragma unroll
    for (int x = 0; x < 4; x++)
#pragma unroll
        for (int y = 0; y < 4; y++)
            atomicAdd(&g_Mf[(size_t)(m0 + ty + 16 * x) * N_ + n0 + tx + 16 * y],
                      acc[x][y]);
}

// ---------------------------------------------------------------------------
// convert M fp32 -> fp16 hi/lo
// ---------------------------------------------------------------------------
__global__ void convert_M() {
    int idx = blockIdx.x * blockDim.x + threadIdx.x;
    if (idx < B_ * N_) {
        float v = g_Mf[idx];
        __half h = __float2half_rn(v);
        __half l = __float2half_rn(v - __half2float(h));
        g_Mh[idx] = h;
        g_Ml[idx] = l;
    }
}

// ---------------------------------------------------------------------------
// Fused: logits GEMM (fp16 3-way split) + cluster softmax + W + ctx partials
// grid (8, 2, 256): x = d-slice (cluster of 8), y = b-half, z = i.
// CTA tile m=128(b) x n=128(d), K=256 (n-reduction) in 8 chunks of 32.
// NOTE: FV appears in TWO roles:
//   fvB (n-indexed, NO b0 offset) — GEMM B operand, reduction over all n
//   fvC (b-indexed, b0 offset)    — ctx epilogue multiplicand
// ---------------------------------------------------------------------------
#define SA_OFF   0
#define SA_STAGE 20480   // hi 128*80 + lo 128*80
#define SA_HL    10240
#define SA_PITCH 80
#define SB_OFF   40960
#define SB_STAGE 17408   // hi 32*272 + lo 32*272
#define SB_HL    8704
#define SB_PITCH 272
#define RED_OFF   75776  // float[128][2]
#define RED1_OFF  76800  // float[8][128]
#define RED2_OFF  80896  // float[8][128]
#define GV_OFF    84992  // float[128]
#define INV_OFF   85504  // float[128]
#define CTXR_OFF  86016  // float[4][128]
#define SMEM_DYN  88064

__global__ void __cluster_dims__(8, 1, 1) __launch_bounds__(256, 2)
fused_attn(const float* __restrict__ FV, float* __restrict__ out) {
    extern __shared__ char smem[];
    const uint32_t sbase = smem_u32(smem);
    const int tid = threadIdx.x;
    const int lane = tid & 31, w = tid >> 5;
    const int i = blockIdx.z;
    const int bhalf = blockIdx.y;
    const int b0 = bhalf * 128;
    const int rank = blockIdx.x;
    const int d0 = rank * 128;
    const float* fvB = FV + (size_t)i * N_ * D_ + d0;                    // n-indexed
    const float* fvC = FV + (size_t)i * N_ * D_ + (size_t)b0 * D_ + d0;  // b-indexed

    float acc[2][8][4];
#pragma unroll
    for (int a = 0; a < 2; a++)
#pragma unroll
        for (int b = 0; b < 8; b++)
#pragma unroll
            for (int c = 0; c < 4; c++) acc[a][b][c] = 0.f;

    // A loads: threads 0-127 hi, 128-255 lo; one row (64B) x4 cp16
    const int ahl = tid >> 7;
    const int arow = tid & 127;
    const char* asrc = ahl ? (const char*)g_Ml : (const char*)g_Mh;
    auto loadA = [&](int c, int s) {
        uint32_t dst0 = sbase + SA_OFF + s * SA_STAGE + ahl * SA_HL + arow * SA_PITCH;
        const char* src = asrc + (size_t)(b0 + arow) * 512 + c * 64;
#pragma unroll
        for (int q = 0; q < 4; q++) cp16(dst0 + q * 16, src + q * 16);
        CP_COMMIT();
    };

    // B loads: chunk = 32 n-rows x 128 floats; 256 threads x 4 float4
    const int rk = tid >> 3;
    const int jb = (tid & 7) * 4;
    float4 bf[4];
    auto loadB = [&](int c) {
        const float4* src = (const float4*)(fvB + (size_t)(c * 32 + rk) * D_);
#pragma unroll
        for (int it = 0; it < 4; it++) bf[it] = src[(jb >> 2) + it * 8];
    };

    loadA(0, 0);
    loadB(0);

    const int m0w = (w >> 1) * 32;
    const int n0w = (w & 1) * 64;
    const int kofB = (lane & 7) | (((lane >> 3) & 1) << 3);
    const int nofB = (lane >> 4) * 8;

#pragma unroll 1
    for (int c = 0; c < 8; c++) {
        const int s = c & 1;
        CP_WAIT0();
        __syncthreads();
        if (c < 7) loadA(c + 1, (c + 1) & 1);

        {
            char* sbb = smem + SB_OFF + s * SB_STAGE + rk * SB_PITCH;
#pragma unroll
            for (int it = 0; it < 4; it++) {
                float4 v = bf[it];
                int j = jb + it * 32;
                __half hx = __float2half_rn(v.x), hy = __float2half_rn(v.y);
                __half hz = __float2half_rn(v.z), hw = __float2half_rn(v.w);
                __half2 p0 = __halves2half2(hx, hy), p1 = __halves2half2(hz, hw);
                uint2 hiw = make_uint2(*(uint32_t*)&p0, *(uint32_t*)&p1);
                __half lx = __float2half_rn(v.x - __half2float(hx));
                __half ly = __float2half_rn(v.y - __half2float(hy));
                __half lz = __float2half_rn(v.z - __half2float(hz));
                __half lw = __float2half_rn(v.w - __half2float(hw));
                __half2 q0 = __halves2half2(lx, ly), q1 = __halves2half2(lz, lw);
                uint2 low = make_uint2(*(uint32_t*)&q0, *(uint32_t*)&q1);
                *(uint2*)(sbb + j * 2) = hiw;
                *(uint2*)(sbb + SB_HL + j * 2) = low;
            }
        }
        if (c < 7) loadB(c + 1);
        __syncthreads();

        const uint32_t sa_h = sbase + SA_OFF + s * SA_STAGE;
        const uint32_t sb_h = sbase + SB_OFF + s * SB_STAGE;
        const uint32_t aBase = sa_h + (m0w + (lane & 15)) * SA_PITCH + (lane >> 4) * 16;

#pragma unroll
        for (int ks = 0; ks < 2; ks++) {
            uint32_t aH[2][4], aL[2][4];
#pragma unroll
            for (int mf = 0; mf < 2; mf++) {
                uint32_t ad = aBase + mf * (16 * SA_PITCH) + ks * 32;
                ldsm_x4(aH[mf], ad);
                ldsm_x4(aL[mf], ad + SA_HL);
            }
#pragma unroll
            for (int nf2 = 0; nf2 < 4; nf2++) {
                uint32_t bad = sb_h + (ks * 16 + kofB) * SB_PITCH +
                               (n0w + nf2 * 16 + nofB) * 2;
                uint32_t bh[4], bl[4];
                ldsm_x4_t(bh, bad);
                ldsm_x4_t(bl, bad + SB_HL);
#pragma unroll
                for (int mf = 0; mf < 2; mf++) {
                    mma16816(acc[mf][2 * nf2],     aH[mf], bh);
                    mma16816(acc[mf][2 * nf2 + 1], aH[mf], bh + 2);
                    mma16816(acc[mf][2 * nf2],     aH[mf], bl);
                    mma16816(acc[mf][2 * nf2 + 1], aH[mf], bl + 2);
                    mma16816(acc[mf][2 * nf2],     aL[mf], bh);
                    mma16816(acc[mf][2 * nf2 + 1], aL[mf], bh + 2);
                }
            }
        }
    }

    // ---------------- register-resident softmax epilogue ----------------
    float* red  = (float*)(smem + RED_OFF);
    float* red1 = (float*)(smem + RED1_OFF);
    float* red2 = (float*)(smem + RED2_OFF);
    float* gv   = (float*)(smem + GV_OFF);
    float* inv  = (float*)(smem + INV_OFF);
    float* ctxr = (float*)(smem + CTXR_OFF);
    __syncthreads();

    float rmax[2][2];
#pragma unroll
    for (int mf = 0; mf < 2; mf++)
#pragma unroll
        for (int h = 0; h < 2; h++) {
            float m = -1e30f;
#pragma unroll
            for (int nf = 0; nf < 8; nf++)
                m = fmaxf(m, fmaxf(acc[mf][nf][2 * h], acc[mf][nf][2 * h + 1]));
            m = fmaxf(m, __shfl_xor_sync(0xffffffffu, m, 1));
            m = fmaxf(m, __shfl_xor_sync(0xffffffffu, m, 2));
            rmax[mf][h] = m;
        }
    if ((lane & 3) == 0) {
#pragma unroll
        for (int mf = 0; mf < 2; mf++)
#pragma unroll
            for (int h = 0; h < 2; h++) {
                int row = m0w + mf * 16 + (lane >> 2) + 8 * h;
                red[row * 2 + (w & 1)] = rmax[mf][h];
            }
    }
    __syncthreads();
    if (tid < 128) {
        float m = fmaxf(red[tid * 2], red[tid * 2 + 1]);
        const uint32_t a = sbase + RED1_OFF + (rank * 128 + tid) * 4;
#pragma unroll
        for (int p = 0; p < 8; p++) st_cluster_f32(a, p, m);
    }
    CLUSTER_ARV(); CLUSTER_WAIT();
    if (tid < 128) {
        float m = -1e30f;
#pragma unroll
        for (int p = 0; p < 8; p++) m = fmaxf(m, red1[p * 128 + tid]);
        gv[tid] = m;
    }
    __syncthreads();

    float rsum[2][2];
#pragma unroll
    for (int mf = 0; mf < 2; mf++)
#pragma unroll
        for (int h = 0; h < 2; h++) {
            int row = m0w + mf * 16 + (lane >> 2) + 8 * h;
            float gm = gv[row];
            float s = 0.f;
#pragma unroll
            for (int nf = 0; nf < 8; nf++) {
                float e0 = __expf(acc[mf][nf][2 * h] - gm);
                float e1 = __expf(acc[mf][nf][2 * h + 1] - gm);
                acc[mf][nf][2 * h] = e0;
                acc[mf][nf][2 * h + 1] = e1;
                s += e0 + e1;
            }
            s += __shfl_xor_sync(0xffffffffu, s, 1);
            s += __shfl_xor_sync(0xffffffffu, s, 2);
            rsum[mf][h] = s;
        }
    if ((lane & 3) == 0) {
#pragma unroll
        for (int mf = 0; mf < 2; mf++)
#pragma unroll
            for (int h = 0; h < 2; h++) {
                int row = m0w + mf * 16 + (lane >> 2) + 8 * h;
                red[row * 2 + (w & 1)] = rsum[mf][h];
            }
    }
    __syncthreads();
    if (tid < 128) {
        float s = red[tid * 2] + red[tid * 2 + 1];
        const uint32_t a = sbase + RED2_OFF + (rank * 128 + tid) * 4;
#pragma unroll
        for (int p = 0; p < 8; p++) st_cluster_f32(a, p, s);
    }
    CLUSTER_ARV(); CLUSTER_WAIT();
    if (tid < 128) {
        float s = 0.f;
#pragma unroll
        for (int p = 0; p < 8; p++) s += red2[p * 128 + tid];
        inv[tid] = __frcp_rn(s);
    }
    __syncthreads();

    // W write + ctx partial (b-indexed FV!)
    float* Wout = out + (size_t)B_ * D_ + (size_t)i * N_ * D_ + (size_t)b0 * D_ + d0;
    float ctxc[16];
#pragma unroll
    for (int j = 0; j < 16; j++) ctxc[j] = 0.f;

#pragma unroll
    for (int mf = 0; mf < 2; mf++)
#pragma unroll
        for (int h = 0; h < 2; h++) {
            int row = m0w + mf * 16 + (lane >> 2) + 8 * h;
            float iv = inv[row];
            const float* fvr = fvC + (size_t)row * D_;
            float* wr = Wout + (size_t)row * D_;
#pragma unroll
            for (int nf = 0; nf < 8; nf++) {
                int col = n0w + nf * 8 + (lane & 3) * 2;
                float w0 = acc[mf][nf][2 * h] * iv;
                float w1 = acc[mf][nf][2 * h + 1] * iv;
                *(float2*)(wr + col) = make_float2(w0, w1);
                float2 f = *(const float2*)(fvr + col);
                ctxc[nf * 2]     = fmaf(w0, f.x, ctxc[nf * 2]);
                ctxc[nf * 2 + 1] = fmaf(w1, f.y, ctxc[nf * 2 + 1]);
            }
        }
#pragma unroll
    for (int j = 0; j < 16; j++) {
        ctxc[j] += __shfl_xor_sync(0xffffffffu, ctxc[j], 4);
        ctxc[j] += __shfl_xor_sync(0xffffffffu, ctxc[j], 8);
        ctxc[j] += __shfl_xor_sync(0xffffffffu, ctxc[j], 16);
    }
    if (lane < 4) {
#pragma unroll
        for (int nf = 0; nf < 8; nf++) {
            int col = n0w + nf * 8 + lane * 2;
            ctxr[(w >> 1) * 128 + col]     = ctxc[nf * 2];
            ctxr[(w >> 1) * 128 + col + 1] = ctxc[nf * 2 + 1];
        }
    }
    __syncthreads();
    if (tid < 128) {
        float s = 0.f;
#pragma unroll
        for (int p = 0; p < 4; p++) s += ctxr[p * 128 + tid];
        g_ctx[bhalf][(size_t)i * D_ + d0 + tid] = s;   // plain store, unique slot
    }
}

// ---------------------------------------------------------------------------
// final: out_ctx[i][d] = g_ctx[0][i][d] + g_ctx[1][i][d]
// ---------------------------------------------------------------------------
__global__ void ctx_reduce(float* __restrict__ out) {
    int idx = blockIdx.x * blockDim.x + threadIdx.x;
    const float4* a = (const float4*)g_ctx[0];
    const float4* b = (const float4*)g_ctx[1];
    float4 va = a[idx], vb = b[idx];
    ((float4*)out)[idx] = make_float4(va.x + vb.x, va.y + vb.y,
                                      va.z + vb.z, va.w + vb.w);
}

// ---------------------------------------------------------------------------
extern "C" void kernel_launch(void* const* d_in, const int* in_sizes, int n_in,
                              void* d_out, int out_size) {
    const float* FV    = (const float*)d_in[0];
    const float* state = (const float*)d_in[1];
    const float* Q     = (const float*)d_in[2];
    const float* Kmat  = (const float*)d_in[3];
    float* out = (float*)d_out;

    cudaFuncSetAttribute(fused_attn, cudaFuncAttributeMaxDynamicSharedMemorySize,
                         SMEM_DYN);

    zero_scratch<<<(B_ * S_ + 255) / 256, 256>>>();
    gemm_nt_sk<<<dim3(S_ / 64, B_ / 64, 8), 256>>>(state, Q);
    gemm_nn_sk<<<dim3(N_ / 64, B_ / 64, 8), 256>>>(Kmat);
    convert_M<<<(B_ * N_ + 255) / 256, 256>>>();
    fused_attn<<<dim3(8, 2, B_), 256, SMEM_DYN>>>(FV, out);
    ctx_reduce<<<(B_ * D_ / 4 + 255) / 256, 256>>>(out);
}